// round 10
// baseline (speedup 1.0000x reference)
#include <cuda_runtime.h>
#include <math.h>

#define NB 32
#define NS 1024
#define ND 256
#define NDS 64
#define NM 3
#define TS 128   // timesteps per out_kernel block

typedef unsigned long long ull;

// ---------------- scratch (device globals; no cudaMalloc allowed) ----------
__device__ float g_xp[(size_t)NB * NS * NM * NDS];   // [B][S][M*DS]  (XW@x + Xb + Hb)
__device__ float g_hn[(size_t)NB * NS * NM * NDS];   // [B][S][M*DS]  (h_new per step)

// ---------------- packed f32x2 helpers -------------------------------------
__device__ __forceinline__ void fma2(ull& acc, ull a, ull b) {
    asm("fma.rn.f32x2 %0, %1, %2, %0;" : "+l"(acc) : "l"(a), "l"(b));
}
__device__ __forceinline__ ull pack2(float x, float y) {
    ull r; asm("mov.b64 %0, {%1, %2};" : "=l"(r) : "f"(x), "f"(y)); return r;
}
__device__ __forceinline__ float2 unpack2(ull v) {
    float2 r; asm("mov.b64 {%0, %1}, %2;" : "=f"(r.x), "=f"(r.y) : "l"(v)); return r;
}
__device__ __forceinline__ float sum2(ull v) { float2 f = unpack2(v); return f.x + f.y; }
__device__ __forceinline__ ull add2(ull a, ull b) {
    ull r; asm("add.rn.f32x2 %0, %1, %2;" : "=l"(r) : "l"(a), "l"(b)); return r;
}

__device__ __forceinline__ float tanh_fast(float x) {
    float y; asm("tanh.approx.f32 %0, %1;" : "=f"(y) : "f"(x)); return y;
}

// ---------------- named barriers (bar.sync has membar.cta semantics) --------
__device__ __forceinline__ void bar_sync(int id, int cnt) {
    asm volatile("bar.sync %0, %1;" :: "r"(id), "r"(cnt) : "memory");
}

// ---------------- cp.async helpers ------------------------------------------
__device__ __forceinline__ void cp_async16(void* smem_dst, const void* gsrc) {
    unsigned s = (unsigned)__cvta_generic_to_shared(smem_dst);
    asm volatile("cp.async.ca.shared.global [%0], [%1], 16;" :: "r"(s), "l"(gsrc));
}
__device__ __forceinline__ void cp_commit() { asm volatile("cp.async.commit_group;"); }
__device__ __forceinline__ void cp_wait1()  { asm volatile("cp.async.wait_group 1;"); }
__device__ __forceinline__ void cp_wait0()  { asm volatile("cp.async.wait_group 0;"); }

// ======================= Kernel 1: xp = XW@x + Xb + Hb =====================
// (unchanged from the 1585us baseline)
__global__ void __launch_bounds__(256) xproj_kernel(
    const float* __restrict__ xa, const float* __restrict__ xv, const float* __restrict__ xl,
    const float* __restrict__ XW, const float* __restrict__ Xb, const float* __restrict__ Hb)
{
    __shared__ __align__(16) float Xs[64][64];   // [t][k]
    __shared__ __align__(16) float Wt[64][64];   // [k][d] (XW transposed)

    const int m  = blockIdx.z;
    const int bb = blockIdx.y;
    const int t0 = blockIdx.x * 64;
    const float* xm = (m == 0) ? xa : ((m == 1) ? xv : xl);

    const int tid = threadIdx.x;
    const int tx = tid & 15, ty = tid >> 4;

    ull acc[4][2] = {};

    const int ldx_row = tid >> 2, ldx_q = tid & 3;
    const int ldw_d = tid & 63, ldw_g = tid >> 6;

    for (int kc = 0; kc < 4; kc++) {
        __syncthreads();
        #pragma unroll
        for (int g = 0; g < 4; g++) {
            int col = ldx_q * 16 + g * 4;
            float4 v = *(const float4*)&xm[((size_t)(bb * NS) + t0 + ldx_row) * ND + kc * 64 + col];
            *(float4*)&Xs[ldx_row][col] = v;
        }
        #pragma unroll
        for (int g = 0; g < 4; g++) {
            int kk = ldw_g * 16 + g * 4;
            float4 w = *(const float4*)&XW[((size_t)(m * NDS + ldw_d)) * ND + kc * 64 + kk];
            Wt[kk + 0][ldw_d] = w.x; Wt[kk + 1][ldw_d] = w.y;
            Wt[kk + 2][ldw_d] = w.z; Wt[kk + 3][ldw_d] = w.w;
        }
        __syncthreads();
        #pragma unroll 16
        for (int kk = 0; kk < 64; kk++) {
            ull bv0 = *(const ull*)&Wt[kk][2 * tx];
            ull bv1 = *(const ull*)&Wt[kk][2 * tx + 32];
            #pragma unroll
            for (int i = 0; i < 4; i++) {
                float a = Xs[ty + 16 * i][kk];
                ull aa = pack2(a, a);
                fma2(acc[i][0], aa, bv0);
                fma2(acc[i][1], aa, bv1);
            }
        }
    }
    #pragma unroll
    for (int i = 0; i < 4; i++) {
        #pragma unroll
        for (int jp = 0; jp < 2; jp++) {
            int d0 = 2 * tx + 32 * jp;
            float2 v = unpack2(acc[i][jp]);
            float2 xb = *(const float2*)&Xb[m * NDS + d0];
            float2 hb = *(const float2*)&Hb[m * NDS + d0];
            v.x += xb.x + hb.x;
            v.y += xb.y + hb.y;
            *(float2*)&g_xp[((size_t)(bb * NS) + t0 + ty + 16 * i) * (NM * NDS) + m * NDS + d0] = v;
        }
    }
}

// ======================= Kernel 2: sequential scan =========================
// grid = 32 (one block per batch element), 416 threads (13 warps).
//   threads 0..383 (warps 0-11): z-partials (phase 1) then su dots (phase 2a)
//   threads 384..415 (warp 12):  z-reduce + tanh + W2 + softmax, xp prefetch
// 3 full named barriers per step; warp 12's chain overlaps warps 0-11's dots.
__global__ void __launch_bounds__(416, 1) scan_kernel(
    const float* __restrict__ W1, const float* __restrict__ b1,
    const float* __restrict__ W2, const float* __restrict__ b2,
    const float* __restrict__ HW, const float* __restrict__ CW)
{
    __shared__ __align__(16) float sh_h[2][NM * NDS];   // double-buffered state
    __shared__ __align__(16) float sh_part[6][NDS];     // z-partials [seg][o]
    __shared__ __align__(16) float sh_xp[2][NM * NDS];  // prefetched xp
    __shared__ float sh_a[12];                          // masked attention

    const int u  = threadIdx.x;
    const int bb = blockIdx.x;
    const float* xp_row0 = g_xp + (size_t)bb * NS * (NM * NDS);

    // ---- init: zero h0, stage xp[0] ----
    if (u < NM * NDS) {
        sh_h[0][u] = 0.0f;
        sh_xp[0][u] = __ldg(xp_row0 + u);
    }

    if (u < 384) {
        // ===================== dot threads =====================
        const int o1  = u & 63;          // phase-1 output
        const int seg = u >> 6;          // phase-1 segment (0..5)
        const int half = u & 1;          // phase-2a half
        const int o2   = u >> 1;         // 0..191 = m*64+d
        const int m4   = o2 >> 6;
        const int s1 = (m4 == 0) ? 1 : 0;
        const int s2 = (m4 == 2) ? 1 : 2;
        const int src = half ? s2 : s1;

        ull w1r[16];   // W1[o1][seg*32 .. +32)
        #pragma unroll
        for (int j = 0; j < 16; j++)
            w1r[j] = *(const ull*)(W1 + (size_t)o1 * (NM * NDS) + seg * 32 + 2 * j);

        ull whw[16];   // HW[m4][d4][half*32 .. +32)
        #pragma unroll
        for (int j = 0; j < 16; j++)
            whw[j] = *(const ull*)(HW + (size_t)o2 * NDS + half * 32 + 2 * j);

        ull wcw[32];   // CW[m4][src][d4][0..64)
        #pragma unroll
        for (int j = 0; j < 32; j++)
            wcw[j] = *(const ull*)(CW + ((size_t)((m4 * NM + src) * NDS + (o2 & 63))) * NDS + 2 * j);

        float* hn_base = g_hn + (size_t)bb * NS * (NM * NDS) + o2;

        bar_sync(0, 416);

        for (int t = 0; t < NS; t++) {
            const int cur = t & 1;
            const float* hbuf = &sh_h[cur][0];

            // ---- phase 1: z-partials ----
            const float* hseg = hbuf + seg * 32;
            ull a1 = 0, a2 = 0;
            #pragma unroll
            for (int j = 0; j < 8; j++) {
                ulonglong2 hv = *(const ulonglong2*)(hseg + 4 * j);
                fma2(a1, hv.x, w1r[2 * j]);
                fma2(a2, hv.y, w1r[2 * j + 1]);
            }
            sh_part[seg][o1] = sum2(a1) + sum2(a2);
            bar_sync(1, 416);

            // ---- phase 2a: HW + CW dots (overlaps warp 12's chain) ----
            const float* hm = hbuf + m4 * 64 + half * 32;
            const float* hs = hbuf + src * 64;
            ull h0 = 0, h1 = 0, c0 = 0, c1 = 0, c2 = 0, c3 = 0;
            #pragma unroll
            for (int j = 0; j < 8; j++) {
                ulonglong2 hv = *(const ulonglong2*)(hm + 4 * j);
                fma2(h0, hv.x, whw[2 * j]);
                fma2(h1, hv.y, whw[2 * j + 1]);
            }
            #pragma unroll
            for (int j = 0; j < 16; j++) {
                ulonglong2 hv = *(const ulonglong2*)(hs + 4 * j);
                if (j & 1) { fma2(c2, hv.x, wcw[2 * j]); fma2(c3, hv.y, wcw[2 * j + 1]); }
                else       { fma2(c0, hv.x, wcw[2 * j]); fma2(c1, hv.y, wcw[2 * j + 1]); }
            }
            bar_sync(2, 416);   // attention ready

            float a = sh_a[m4 * 3 + src];
            float val = sum2(h0) + sum2(h1)
                      + a * (sum2(c0) + sum2(c1) + sum2(c2) + sum2(c3));
            val += __shfl_xor_sync(0xffffffffu, val, 1);   // combine halves
            if (half == 0) {
                float su = val + sh_xp[cur][o2];
                float hn = su / (1.0f + __expf(-su));       // silu
                sh_h[cur ^ 1][o2] = hn;
                hn_base[(size_t)t * (NM * NDS)] = hn;
            }
            bar_sync(0, 416);   // step end
        }
    } else {
        // ===================== gating warp (warp 12) =====================
        const int l = u - 384;   // lane 0..31; owns z[2l], z[2l+1]

        const float2 b1r = *(const float2*)(b1 + 2 * l);
        ull w2r[9];
        #pragma unroll
        for (int p = 0; p < 9; p++)
            w2r[p] = *(const ull*)(W2 + (size_t)p * NDS + 2 * l);
        float b2r[9];
        #pragma unroll
        for (int p = 0; p < 9; p++) b2r[p] = b2[p];

        bar_sync(0, 416);

        for (int t = 0; t < NS; t++) {
            bar_sync(1, 416);   // z-partials ready

            // reduce 6 partials + b1, tanh
            float2 v = b1r;
            #pragma unroll
            for (int s = 0; s < 6; s++) {
                float2 pp = *(const float2*)&sh_part[s][2 * l];
                v.x += pp.x; v.y += pp.y;
            }
            ull zp = pack2(tanh_fast(v.x), tanh_fast(v.y));

            // 9 W2 dots (packed), then 5-round parallel shfl tree
            float s9[9];
            #pragma unroll
            for (int p = 0; p < 9; p++) {
                ull acc = 0; fma2(acc, zp, w2r[p]);
                s9[p] = sum2(acc);
            }
            #pragma unroll
            for (int off = 16; off; off >>= 1) {
                #pragma unroll
                for (int p = 0; p < 9; p++)
                    s9[p] += __shfl_xor_sync(0xffffffffu, s9[p], off);
            }

            // softmax rows (mask AFTER softmax per reference); raws are small,
            // no max-subtraction needed
            if (l < 3) {
                float e0 = __expf(s9[3 * l + 0] + b2r[3 * l + 0]);
                float e1 = __expf(s9[3 * l + 1] + b2r[3 * l + 1]);
                float e2 = __expf(s9[3 * l + 2] + b2r[3 * l + 2]);
                float inv = 1.0f / (e0 + e1 + e2);
                sh_a[3 * l + 0] = (l == 0) ? 0.0f : e0 * inv;
                sh_a[3 * l + 1] = (l == 1) ? 0.0f : e1 * inv;
                sh_a[3 * l + 2] = (l == 2) ? 0.0f : e2 * inv;
            }
            cp_wait0();          // xp for THIS step (issued last step) is in smem
            bar_sync(2, 416);    // publish attention (+ xp visibility)

            // prefetch xp for step t+1 into the other buffer
            {
                int tn = (t + 1 < NS) ? (t + 1) : t;
                const float* gsrc = xp_row0 + (size_t)tn * (NM * NDS);
                float* sdst = &sh_xp[(t + 1) & 1][0];
                cp_async16(sdst + 4 * l, gsrc + 4 * l);          // bytes [0,512)
                if (l < 16)
                    cp_async16(sdst + 128 + 4 * l, gsrc + 128 + 4 * l); // [512,768)
                cp_commit();
            }
            bar_sync(0, 416);    // step end
        }
    }
}

// ======================= Kernel 3: y = OW@h_new + Ob; out = LN(y + x) ======
// (unchanged from the 1585us baseline)
__global__ void __launch_bounds__(256) out_kernel(
    const float* __restrict__ xa, const float* __restrict__ xv, const float* __restrict__ xl,
    const float* __restrict__ OW, const float* __restrict__ Ob,
    const float* __restrict__ lng, const float* __restrict__ lnb,
    float* __restrict__ out)
{
    __shared__ __align__(16) float sh_ht[2][8][NDS];
    __shared__ float sh_red[2][8][2];

    const int tid = threadIdx.x;
    const int t0  = blockIdx.x * TS;
    const int bb  = blockIdx.y;
    const int m   = blockIdx.z;
    const float* xm = (m == 0) ? xa : ((m == 1) ? xv : xl);

    ull ow[32];
    #pragma unroll
    for (int j = 0; j < 32; j++)
        ow[j] = *(const ull*)(OW + ((size_t)m * ND + tid) * NDS + 2 * j);
    const float ob = Ob[m * ND + tid];
    const float gg = lng[m * ND + tid];
    const float be = lnb[m * ND + tid];

    const float* hn_base = g_hn + ((size_t)(bb * NS + t0)) * (NM * NDS) + m * NDS;
    const float* x_base  = xm + ((size_t)bb * NS + t0) * ND;
    float* o_base = out + ((size_t)m * NB + bb) * (size_t)NS * ND + (size_t)t0 * ND;

    const int ptt = tid >> 4;
    const int pq  = tid & 15;

    if (tid < 128) {
        int tc = min(0 * 8 + ptt, TS - 1);
        cp_async16(&sh_ht[0][ptt][pq * 4], hn_base + (size_t)tc * (NM * NDS) + pq * 4);
    }
    cp_commit();

    const int NG = TS / 8;
    for (int g = 0; g < NG; g++) {
        const int buf = g & 1;
        if (tid < 128) {
            int tc = min((g + 1) * 8 + ptt, TS - 1);
            cp_async16(&sh_ht[buf ^ 1][ptt][pq * 4], hn_base + (size_t)tc * (NM * NDS) + pq * 4);
        }
        cp_commit();
        cp_wait1();
        __syncthreads();

        #pragma unroll
        for (int k = 0; k < 8; k++) {
            const int t = g * 8 + k;
            float xval = __ldg(x_base + (size_t)t * ND + tid);

            ull acc = 0;
            #pragma unroll
            for (int j = 0; j < 32; j++)
                fma2(acc, *(const ull*)&sh_ht[buf][k][2 * j], ow[j]);
            float v = sum2(acc) + ob + xval;

            float s = v, ss = v * v;
            #pragma unroll
            for (int off = 16; off; off >>= 1) {
                s  += __shfl_xor_sync(0xffffffffu, s, off);
                ss += __shfl_xor_sync(0xffffffffu, ss, off);
            }
            const int w = tid >> 5, lw = tid & 31;
            const int rb = t & 1;
            if (lw == 0) { sh_red[rb][w][0] = s; sh_red[rb][w][1] = ss; }
            __syncthreads();
            float S = 0.0f, SS = 0.0f;
            #pragma unroll
            for (int w2 = 0; w2 < 8; w2++) { S += sh_red[rb][w2][0]; SS += sh_red[rb][w2][1]; }
            float mu  = S * (1.0f / 256.0f);
            float var = SS * (1.0f / 256.0f) - mu * mu;
            float r   = rsqrtf(var + 1e-5f);
            o_base[(size_t)t * ND + tid] = (v - mu) * r * gg + be;
        }
    }
}

// =============================== launch ====================================
extern "C" void kernel_launch(void* const* d_in, const int* in_sizes, int n_in,
                              void* d_out, int out_size) {
    const float* xa  = (const float*)d_in[0];
    const float* xv  = (const float*)d_in[1];
    const float* xl  = (const float*)d_in[2];
    const float* XW  = (const float*)d_in[3];
    const float* Xb  = (const float*)d_in[4];
    const float* HW  = (const float*)d_in[5];
    const float* Hb  = (const float*)d_in[6];
    const float* OW  = (const float*)d_in[7];
    const float* Ob  = (const float*)d_in[8];
    const float* CW  = (const float*)d_in[9];
    const float* W1  = (const float*)d_in[10];
    const float* b1  = (const float*)d_in[11];
    const float* W2  = (const float*)d_in[12];
    const float* b2  = (const float*)d_in[13];
    const float* lng = (const float*)d_in[14];
    const float* lnb = (const float*)d_in[15];
    float* out = (float*)d_out;

    dim3 gA(NS / 64, NB, NM);
    xproj_kernel<<<gA, 256>>>(xa, xv, xl, XW, Xb, Hb);

    scan_kernel<<<NB, 416>>>(W1, b1, W2, b2, HW, CW);

    dim3 gC(NS / TS, NB, NM);
    out_kernel<<<gC, 256>>>(xa, xv, xl, OW, Ob, lng, lnb, out);
}